// round 16
// baseline (speedup 1.0000x reference)
#include <cuda_runtime.h>
#include <cuda_fp16.h>
#include <math.h>
#include <stdint.h>

#define HIDDEN   2048
#define HEADS    16
#define HEAD_DIM 128
#define BATCH    2
#define SEQ      2048
#define MROWS    (BATCH * SEQ)   // 4096

// ---------------------------------------------------------------------------
// Scratch (allocation-free: __device__ globals)
// ---------------------------------------------------------------------------
__device__ __half g_qh [BATCH * HEADS * SEQ * HEAD_DIM];   // pre-scaled
__device__ __half g_kh [BATCH * HEADS * SEQ * HEAD_DIM];
__device__ __half g_vh [BATCH * HEADS * SEQ * HEAD_DIM];
__device__ __half g_aoh[MROWS * HIDDEN];

__device__ __half g_xh [MROWS * HIDDEN];
__device__ __half g_wqh[HIDDEN * HIDDEN];
__device__ __half g_wkh[HIDDEN * HIDDEN];
__device__ __half g_wvh[HIDDEN * HIDDEN];
__device__ __half g_woh[HIDDEN * HIDDEN];

// ---------------------------------------------------------------------------
// PTX helpers (baseline sm_80 features — harness targets plain sm_103)
// ---------------------------------------------------------------------------
__device__ __forceinline__ uint32_t smem_u32(const void* p) {
    return (uint32_t)__cvta_generic_to_shared(p);
}

#define CP_ASYNC16(dst_u32, src_ptr) \
    asm volatile("cp.async.cg.shared.global [%0], [%1], 16;" \
                 :: "r"(dst_u32), "l"(src_ptr))
#define CP_ASYNC_COMMIT() asm volatile("cp.async.commit_group;")
#define CP_ASYNC_WAIT0()  asm volatile("cp.async.wait_group 0;" ::: "memory")
#define CP_ASYNC_WAIT1()  asm volatile("cp.async.wait_group 1;" ::: "memory")

#define LDSM_X4(r, addr) \
    asm volatile("ldmatrix.sync.aligned.m8n8.x4.shared.b16 {%0,%1,%2,%3}, [%4];" \
                 : "=r"((r)[0]), "=r"((r)[1]), "=r"((r)[2]), "=r"((r)[3]) \
                 : "r"(addr))

#define LDSM_X4_T(r, addr) \
    asm volatile("ldmatrix.sync.aligned.m8n8.x4.trans.shared.b16 {%0,%1,%2,%3}, [%4];" \
                 : "=r"((r)[0]), "=r"((r)[1]), "=r"((r)[2]), "=r"((r)[3]) \
                 : "r"(addr))

#define MMA_F16(d, a, b) \
    asm volatile("mma.sync.aligned.m16n8k16.row.col.f32.f16.f16.f32 " \
                 "{%0,%1,%2,%3}, {%4,%5,%6,%7}, {%8,%9}, {%0,%1,%2,%3};" \
                 : "+f"((d)[0]), "+f"((d)[1]), "+f"((d)[2]), "+f"((d)[3]) \
                 : "r"((a)[0]), "r"((a)[1]), "r"((a)[2]), "r"((a)[3]), \
                   "r"((b)[0]), "r"((b)[1]))

__device__ __forceinline__ float ex2(float x) {
    float y;
    asm("ex2.approx.ftz.f32 %0, %1;" : "=f"(y) : "f"(x));
    return y;
}
__device__ __forceinline__ uint32_t pack_h2(float a, float b) {
    __half2 p = __floats2half2_rn(a, b);
    return *reinterpret_cast<uint32_t*>(&p);
}

// ---------------------------------------------------------------------------
// Fused prep: x, wq, wk, wv, wo -> fp16 (single). One launch.
// ---------------------------------------------------------------------------
#define X4C (1 << 21)   // MROWS*HIDDEN/4
#define W4C (1 << 20)   // HIDDEN*HIDDEN/4

__global__ __launch_bounds__(256)
void prep_kernel(const float* __restrict__ x,  __half* __restrict__ xh,
                 const float* __restrict__ wq, __half* __restrict__ wqh,
                 const float* __restrict__ wk, __half* __restrict__ wkh,
                 const float* __restrict__ wv, __half* __restrict__ wvh,
                 const float* __restrict__ wo, __half* __restrict__ woh)
{
    const int i = blockIdx.x * blockDim.x + threadIdx.x;
    const float* src;
    __half* dst;
    int e;
    if (i < X4C) {
        src = x; dst = xh; e = i;
    } else {
        const int j = i - X4C;
        const int w = j >> 20;
        e = j & (W4C - 1);
        src = (w == 0) ? wq : (w == 1) ? wk : (w == 2) ? wv : wo;
        dst = (w == 0) ? wqh : (w == 1) ? wkh : (w == 2) ? wvh : woh;
    }
    float4 v = reinterpret_cast<const float4*>(src)[e];
    uint32_t* dp = reinterpret_cast<uint32_t*>(dst) + e * 2;
    dp[0] = pack_h2(v.x, v.y);
    dp[1] = pack_h2(v.z, v.w);
}

// ---------------------------------------------------------------------------
// HMMA fp16 GEMM, single-term weights. KCHUNK=32, ROWB=80, 4-STAGE ring,
// TWO chunks per barrier (64-MMA bursts, flash-matched granularity):
//   iter cc: wait_group0 -> barrier -> prefetch cc+2,cc+3 (stages of the
//   chunks consumed last iteration) -> compute cc, cc+1.
// MODE 0: fp32 out row-major. MODE 1: fused QKV (N=3*HIDDEN, region scatter).
// CTA 128x128, 256 threads, 2 CTAs/SM (regs<=128, smem 80KB).
// ---------------------------------------------------------------------------
#define GK      HIDDEN
#define KCHUNK  32
#define NCHNK   (GK / KCHUNK)    // 64
#define ROWB    80
#define TILE_B  (128 * ROWB)     // 10240
#define STAGE_B (2 * TILE_B)     // A + B = 20480
#define SMEM_GEMM (4 * STAGE_B)  // 81920

template <int MODE>
__global__ __launch_bounds__(256, 2)
void gemm_f16_kernel(const __half* __restrict__ Ah,
                     const __half* __restrict__ W0,
                     const __half* __restrict__ W1,
                     const __half* __restrict__ W2,
                     const float* __restrict__ b0p,
                     const float* __restrict__ b1p,
                     const float* __restrict__ b2p,
                     float* __restrict__ C,
                     __half* __restrict__ C0,
                     __half* __restrict__ C1,
                     __half* __restrict__ C2,
                     float qscale)
{
    extern __shared__ char smem[];
    const uint32_t sb = smem_u32(smem);
    const int tid = threadIdx.x;
    const int wid = tid >> 5;
    const int lid = tid & 31;

    const int rowBase = blockIdx.y * 128;
    const int colBase = blockIdx.x * 128;

    // Region select (uniform per CTA)
    const __half* Wsel;
    const float*  bsel;
    float outScale = 1.0f;
    int colLocal = colBase;
    if (MODE == 1) {
        const int region = colBase >> 11;
        colLocal = colBase & (HIDDEN - 1);
        Wsel = (region == 0) ? W0 : (region == 1) ? W1 : W2;
        bsel = (region == 0) ? b0p : (region == 1) ? b1p : b2p;
        if (region == 0) outScale = qscale;
    } else {
        Wsel = W0; bsel = b0p;
    }

    // Loader: 2 threads per row, 2x16B each
    const int lr  = tid >> 1;
    const int lc2 = (tid & 1) * 2;
    const __half* pA = Ah   + (size_t)(rowBase  + lr) * GK + lc2 * 8;
    const __half* pB = Wsel + (size_t)(colLocal + lr) * GK + lc2 * 8;
    const uint32_t soff = (uint32_t)lr * ROWB + lc2 * 16;

    auto load_chunk = [&](int c) {     // stage = c & 3; no commit inside
        const uint32_t sg = sb + (c & 3) * STAGE_B;
        const int e = c * KCHUNK;
        CP_ASYNC16(sg + soff,                 pA + e);
        CP_ASYNC16(sg + soff + 16,            pA + e + 8);
        CP_ASYNC16(sg + TILE_B + soff,        pB + e);
        CP_ASYNC16(sg + TILE_B + soff + 16,   pB + e + 8);
    };

    const int mbase = (wid >> 2) * 64;
    const int nbase = (wid & 3) * 32;

    const int mi   = lid >> 3;
    const int tr   = lid & 7;
    const int a_r8 = (mi & 1) * 8;
    const int a_k8 = (mi >> 1) * 8;
    const int b_n8 = (mi >> 1) * 8;
    const int b_k8 = (mi & 1) * 8;

    float acc[4][4][4];
#pragma unroll
    for (int i = 0; i < 4; i++)
#pragma unroll
        for (int j = 0; j < 4; j++)
#pragma unroll
            for (int r = 0; r < 4; r++) acc[i][j][r] = 0.0f;

    load_chunk(0); load_chunk(1); CP_ASYNC_COMMIT();

    for (int cc = 0; cc < NCHNK; cc += 2) {
        CP_ASYNC_WAIT0();
        __syncthreads();
        if (cc + 2 < NCHNK) {
            load_chunk(cc + 2); load_chunk(cc + 3); CP_ASYNC_COMMIT();
        }

        // Compute chunks cc and cc+1 as one 128-MMA burst (per warp: 64)
#pragma unroll
        for (int h = 0; h < 2; h++) {
            const uint32_t sg = sb + ((cc + h) & 3) * STAGE_B;
#pragma unroll
            for (int ks = 0; ks < 2; ks++) {
                uint32_t B_r[8];
#pragma unroll
                for (int bt = 0; bt < 2; bt++) {
                    const uint32_t off =
                        (uint32_t)(nbase + bt * 16 + b_n8 + tr) * ROWB +
                        (uint32_t)(ks * 16 + b_k8) * 2;
                    LDSM_X4(&B_r[bt * 4], sg + TILE_B + off);
                }
#pragma unroll
                for (int mt = 0; mt < 4; mt++) {
                    uint32_t A_r[4];
                    const uint32_t off =
                        (uint32_t)(mbase + mt * 16 + a_r8 + tr) * ROWB +
                        (uint32_t)(ks * 16 + a_k8) * 2;
                    LDSM_X4(A_r, sg + off);
#pragma unroll
                    for (int nt = 0; nt < 4; nt++)
                        MMA_F16(acc[mt][nt], A_r, &B_r[nt * 2]);
                }
            }
        }
    }

    // ---- epilogue ----
    __half* Cout = nullptr;
    if (MODE == 1) {
        const int region = colBase >> 11;
        Cout = (region == 0) ? C0 : (region == 1) ? C1 : C2;
    }
    const int er = lid >> 2;
    const int ec = (lid & 3) * 2;
#pragma unroll
    for (int mt = 0; mt < 4; mt++) {
#pragma unroll
        for (int nt = 0; nt < 4; nt++) {
            const int col = colLocal + nbase + nt * 8 + ec;
            const float b0 = __ldg(&bsel[col]);
            const float b1 = __ldg(&bsel[col + 1]);
#pragma unroll
            for (int h = 0; h < 2; h++) {
                const int row = rowBase + mbase + mt * 16 + er + h * 8;
                const float vx = (acc[mt][nt][h * 2 + 0] + b0) * outScale;
                const float vy = (acc[mt][nt][h * 2 + 1] + b1) * outScale;
                if (MODE == 0) {
                    float2 v; v.x = vx; v.y = vy;
                    *reinterpret_cast<float2*>(C + (size_t)row * HIDDEN + col) = v;
                } else {
                    const int b  = row >> 11;
                    const int s  = row & (SEQ - 1);
                    const int hh = col >> 7;
                    const int d  = col & (HEAD_DIM - 1);
                    const size_t idx =
                        ((size_t)(b * HEADS + hh) * SEQ + s) * HEAD_DIM + d;
                    *reinterpret_cast<uint32_t*>(Cout + idx) = pack_h2(vx, vy);
                }
            }
        }
    }
}

// ---------------------------------------------------------------------------
// HMMA flash attention, fp16, static-max softmax, 32 q-rows/warp, BQ=128.
// (unchanged — at ~295 TF/s, near the legacy-HMMA pipe ceiling)
// ---------------------------------------------------------------------------
#define FPIT     272
#define F_QB     (128 * FPIT)
#define F_KVT    (64 * FPIT)
#define F_STAGE  (2 * F_KVT)
#define F_ST0    F_QB
#define SMEM_FLASH (F_QB + 2 * F_STAGE)  // 104448
#define NT       (SEQ / 64)

__global__ __launch_bounds__(128, 2)
void flash_hmma_kernel(const __half* __restrict__ qh,
                       const __half* __restrict__ kh,
                       const __half* __restrict__ vh,
                       __half* __restrict__ aoh)
{
    extern __shared__ char smem[];
    const uint32_t sb = smem_u32(smem);
    const int tid = threadIdx.x;
    const int wid = tid >> 5;
    const int lid = tid & 31;

    const int bh = blockIdx.y;
    const int q0 = blockIdx.x * 128;
    const int b  = bh >> 4;
    const int hh = bh & (HEADS - 1);
    const size_t hd = (size_t)bh * SEQ * HEAD_DIM;

    const int mi   = lid >> 3;
    const int tr   = lid & 7;
    const int a_r8 = (mi & 1) * 8;
    const int a_k8 = (mi >> 1) * 8;
    const int b_n8 = (mi >> 1) * 8;
    const int b_k8 = (mi & 1) * 8;
    const int w32  = wid * 32;

    auto load_q = [&]() {
        const size_t srow = hd + (size_t)(q0 + tid) * HEAD_DIM;
        const uint32_t d0 = sb + (uint32_t)tid * FPIT;
#pragma unroll
        for (int j = 0; j < 16; j++)
            CP_ASYNC16(d0 + j * 16, qh + srow + j * 8);
    };
    const int l_lr = tid >> 1, l_lc = tid & 1;
    auto load_kv = [&](int kt) {
        const size_t srow = hd + (size_t)(kt * 64 + l_lr) * HEAD_DIM + l_lc * 64;
        const uint32_t base = sb + F_ST0 + (kt & 1) * F_STAGE +
                              (uint32_t)l_lr * FPIT + l_lc * 128;
#pragma unroll
        for (int j = 0; j < 8; j++) {
            CP_ASYNC16(base + j * 16,         kh + srow + j * 8);
            CP_ASYNC16(base + F_KVT + j * 16, vh + srow + j * 8);
        }
    };

    auto qk_tile = [&](float (&dst)[16][4], int kt) {
        const uint32_t kbase = sb + F_ST0 + (kt & 1) * F_STAGE;
#pragma unroll
        for (int j = 0; j < 16; j++)
#pragma unroll
            for (int r = 0; r < 4; r++) dst[j][r] = 0.0f;
#pragma unroll
        for (int ks = 0; ks < 8; ks++) {
            uint32_t qf[2][4];
#pragma unroll
            for (int qg = 0; qg < 2; qg++)
                LDSM_X4(qf[qg], sb + (uint32_t)(w32 + qg * 16 + a_r8 + tr) * FPIT +
                                 (uint32_t)(ks * 16 + a_k8) * 2);
#pragma unroll
            for (int ng = 0; ng < 4; ng++) {
                uint32_t kf[4];
                LDSM_X4(kf, kbase + (uint32_t)(ng * 16 + b_n8 + tr) * FPIT +
                             (uint32_t)(ks * 16 + b_k8) * 2);
#pragma unroll
                for (int qg = 0; qg < 2; qg++) {
                    MMA_F16(dst[qg * 8 + 2 * ng],     qf[qg], &kf[0]);
                    MMA_F16(dst[qg * 8 + 2 * ng + 1], qf[qg], &kf[2]);
                }
            }
        }
    };

    float oacc[2][16][4];
#pragma unroll
    for (int g = 0; g < 2; g++)
#pragma unroll
        for (int i = 0; i < 16; i++)
#pragma unroll
            for (int r = 0; r < 4; r++) oacc[g][i][r] = 0.0f;

    float m[4];
    float rl[4] = {0.f, 0.f, 0.f, 0.f};

    auto sm_pv = [&](float (&cur)[16][4], int t) {
        const uint32_t vbase = sb + F_ST0 + (t & 1) * F_STAGE + F_KVT;
#pragma unroll
        for (int k2 = 0; k2 < 4; k2++) {
            uint32_t ph[2][4];
#pragma unroll
            for (int qg = 0; qg < 2; qg++) {
#pragma unroll
                for (int half = 0; half < 2; half++) {
                    const int j = 2 * k2 + half;
                    float p0 = ex2(cur[qg * 8 + j][0] - m[qg * 2]);
                    float p1 = ex2(cur[qg * 8 + j][1] - m[qg * 2]);
                    float p2 = ex2(cur[qg * 8 + j][2] - m[qg * 2 + 1]);
                    float p3 = ex2(cur[qg * 8 + j][3] - m[qg * 2 + 1]);
                    rl[qg * 2]     += p0 + p1;
                    rl[qg * 2 + 1] += p2 + p3;
                    ph[qg][half * 2 + 0] = pack_h2(p0, p1);
                    ph[qg][half * 2 + 1] = pack_h2(p2, p3);
                }
            }
#pragma unroll
            for (int nv = 0; nv < 8; nv++) {
                uint32_t vf[4];
                LDSM_X4_T(vf, vbase + (uint32_t)(k2 * 16 + a_r8 + tr) * FPIT +
                               (uint32_t)(nv * 16 + a_k8) * 2);
#pragma unroll
                for (int qg = 0; qg < 2; qg++) {
                    MMA_F16(oacc[qg][2 * nv],     ph[qg], &vf[0]);
                    MMA_F16(oacc[qg][2 * nv + 1], ph[qg], &vf[2]);
                }
            }
        }
    };

    float sacc[16][4];

    load_q(); load_kv(0); CP_ASYNC_COMMIT();
    load_kv(1); CP_ASYNC_COMMIT();
    CP_ASYNC_WAIT1();
    __syncthreads();

    qk_tile(sacc, 0);
#pragma unroll
    for (int qg = 0; qg < 2; qg++) {
        float mx0 = -1e30f, mx1 = -1e30f;
#pragma unroll
        for (int j = 0; j < 8; j++) {
            mx0 = fmaxf(mx0, fmaxf(sacc[qg * 8 + j][0], sacc[qg * 8 + j][1]));
            mx1 = fmaxf(mx1, fmaxf(sacc[qg * 8 + j][2], sacc[qg * 8 + j][3]));
        }
        mx0 = fmaxf(mx0, __shfl_xor_sync(0xffffffffu, mx0, 1));
        mx0 = fmaxf(mx0, __shfl_xor_sync(0xffffffffu, mx0, 2));
        mx1 = fmaxf(mx1, __shfl_xor_sync(0xffffffffu, mx1, 1));
        mx1 = fmaxf(mx1, __shfl_xor_sync(0xffffffffu, mx1, 2));
        m[qg * 2] = mx0; m[qg * 2 + 1] = mx1;
    }
    sm_pv(sacc, 0);
    __syncthreads();
    load_kv(2); CP_ASYNC_COMMIT();

    for (int t = 1; t < NT; t++) {
        if (t == NT - 1) { CP_ASYNC_WAIT0(); } else { CP_ASYNC_WAIT1(); }
        __syncthreads();
        qk_tile(sacc, t);
        sm_pv(sacc, t);
        __syncthreads();
        if (t + 2 < NT) { load_kv(t + 2); CP_ASYNC_COMMIT(); }
    }

#pragma unroll
    for (int i = 0; i < 4; i++) {
        rl[i] += __shfl_xor_sync(0xffffffffu, rl[i], 1);
        rl[i] += __shfl_xor_sync(0xffffffffu, rl[i], 2);
    }
    const int dc = 2 * (lid & 3);
#pragma unroll
    for (int qg = 0; qg < 2; qg++) {
        const float i0 = 1.0f / rl[qg * 2];
        const float i1 = 1.0f / rl[qg * 2 + 1];
        const int r0 = w32 + qg * 16 + (lid >> 2);
        const size_t ob0 = ((size_t)b * SEQ + (q0 + r0)) * HIDDEN + hh * HEAD_DIM;
        const size_t ob1 = ((size_t)b * SEQ + (q0 + r0 + 8)) * HIDDEN + hh * HEAD_DIM;
#pragma unroll
        for (int nt = 0; nt < 16; nt++) {
            const int d = nt * 8 + dc;
            *reinterpret_cast<uint32_t*>(aoh + ob0 + d) =
                pack_h2(oacc[qg][nt][0] * i0, oacc[qg][nt][1] * i0);
            *reinterpret_cast<uint32_t*>(aoh + ob1 + d) =
                pack_h2(oacc[qg][nt][2] * i1, oacc[qg][nt][3] * i1);
        }
    }
}

// ---------------------------------------------------------------------------
extern "C" void kernel_launch(void* const* d_in, const int* in_sizes, int n_in,
                              void* d_out, int out_size)
{
    const float* x  = (const float*)d_in[0];
    const float* wq = (const float*)d_in[1];
    const float* bq = (const float*)d_in[2];
    const float* wk = (const float*)d_in[3];
    const float* bk = (const float*)d_in[4];
    const float* wv = (const float*)d_in[5];
    const float* bv = (const float*)d_in[6];
    const float* wo = (const float*)d_in[7];
    const float* bo = (const float*)d_in[8];
    float* out = (float*)d_out;

    __half *qh, *kh, *vh, *aoh, *xh, *wqh, *wkh, *wvh, *woh;
    cudaGetSymbolAddress((void**)&qh,  g_qh);
    cudaGetSymbolAddress((void**)&kh,  g_kh);
    cudaGetSymbolAddress((void**)&vh,  g_vh);
    cudaGetSymbolAddress((void**)&aoh, g_aoh);
    cudaGetSymbolAddress((void**)&xh,  g_xh);
    cudaGetSymbolAddress((void**)&wqh, g_wqh);
    cudaGetSymbolAddress((void**)&wkh, g_wkh);
    cudaGetSymbolAddress((void**)&wvh, g_wvh);
    cudaGetSymbolAddress((void**)&woh, g_woh);

    const int prep_blocks = (X4C + 4 * W4C + 255) / 256;
    prep_kernel<<<prep_blocks, 256>>>(x, xh, wq, wqh, wk, wkh, wv, wvh, wo, woh);

    cudaFuncSetAttribute((const void*)gemm_f16_kernel<0>,
                         cudaFuncAttributeMaxDynamicSharedMemorySize, SMEM_GEMM);
    cudaFuncSetAttribute((const void*)gemm_f16_kernel<1>,
                         cudaFuncAttributeMaxDynamicSharedMemorySize, SMEM_GEMM);
    cudaFuncSetAttribute((const void*)flash_hmma_kernel,
                         cudaFuncAttributeMaxDynamicSharedMemorySize, SMEM_FLASH);

    const float qscale = 0.12751879721578587f;   // 1/sqrt(128) * log2(e)

    // Fused QKV projection: N = 3*HIDDEN
    const dim3 gqkv(3 * HIDDEN / 128, MROWS / 128);   // (48, 32)
    gemm_f16_kernel<1><<<gqkv, 256, SMEM_GEMM>>>(
        xh, wqh, wkh, wvh, bq, bk, bv,
        nullptr, qh, kh, vh, qscale);

    const dim3 fg(SEQ / 128, BATCH * HEADS);          // (16, 32)
    flash_hmma_kernel<<<fg, 128, SMEM_FLASH>>>(qh, kh, vh, aoh);

    // O projection: fp32 out, single-term
    const dim3 go(HIDDEN / 128, MROWS / 128);         // (16, 32)
    gemm_f16_kernel<0><<<go, 256, SMEM_GEMM>>>(
        aoh, woh, nullptr, nullptr, bo, nullptr, nullptr,
        out, nullptr, nullptr, nullptr, 1.0f);
}

// round 17
// speedup vs baseline: 1.0394x; 1.0394x over previous
#include <cuda_runtime.h>
#include <cuda_fp16.h>
#include <math.h>
#include <stdint.h>

#define HIDDEN   2048
#define HEADS    16
#define HEAD_DIM 128
#define BATCH    2
#define SEQ      2048
#define MROWS    (BATCH * SEQ)   // 4096

// ---------------------------------------------------------------------------
// Scratch (allocation-free: __device__ globals)
// ---------------------------------------------------------------------------
__device__ __half g_qh [BATCH * HEADS * SEQ * HEAD_DIM];   // pre-scaled
__device__ __half g_kh [BATCH * HEADS * SEQ * HEAD_DIM];
__device__ __half g_vh [BATCH * HEADS * SEQ * HEAD_DIM];
__device__ __half g_aoh[MROWS * HIDDEN];

__device__ __half g_xh [MROWS * HIDDEN];
__device__ __half g_wqh[HIDDEN * HIDDEN];
__device__ __half g_wkh[HIDDEN * HIDDEN];
__device__ __half g_wvh[HIDDEN * HIDDEN];
__device__ __half g_woh[HIDDEN * HIDDEN];

// ---------------------------------------------------------------------------
// PTX helpers (baseline sm_80 features — harness targets plain sm_103)
// ---------------------------------------------------------------------------
__device__ __forceinline__ uint32_t smem_u32(const void* p) {
    return (uint32_t)__cvta_generic_to_shared(p);
}

#define CP_ASYNC16(dst_u32, src_ptr) \
    asm volatile("cp.async.cg.shared.global [%0], [%1], 16;" \
                 :: "r"(dst_u32), "l"(src_ptr))
#define CP_ASYNC_COMMIT() asm volatile("cp.async.commit_group;")
#define CP_ASYNC_WAIT0()  asm volatile("cp.async.wait_group 0;" ::: "memory")
#define CP_ASYNC_WAIT1()  asm volatile("cp.async.wait_group 1;" ::: "memory")

#define LDSM_X4(r, addr) \
    asm volatile("ldmatrix.sync.aligned.m8n8.x4.shared.b16 {%0,%1,%2,%3}, [%4];" \
                 : "=r"((r)[0]), "=r"((r)[1]), "=r"((r)[2]), "=r"((r)[3]) \
                 : "r"(addr))

#define LDSM_X4_T(r, addr) \
    asm volatile("ldmatrix.sync.aligned.m8n8.x4.trans.shared.b16 {%0,%1,%2,%3}, [%4];" \
                 : "=r"((r)[0]), "=r"((r)[1]), "=r"((r)[2]), "=r"((r)[3]) \
                 : "r"(addr))

#define MMA_F16(d, a, b) \
    asm volatile("mma.sync.aligned.m16n8k16.row.col.f32.f16.f16.f32 " \
                 "{%0,%1,%2,%3}, {%4,%5,%6,%7}, {%8,%9}, {%0,%1,%2,%3};" \
                 : "+f"((d)[0]), "+f"((d)[1]), "+f"((d)[2]), "+f"((d)[3]) \
                 : "r"((a)[0]), "r"((a)[1]), "r"((a)[2]), "r"((a)[3]), \
                   "r"((b)[0]), "r"((b)[1]))

__device__ __forceinline__ float ex2(float x) {
    float y;
    asm("ex2.approx.ftz.f32 %0, %1;" : "=f"(y) : "f"(x));
    return y;
}
__device__ __forceinline__ uint32_t pack_h2(float a, float b) {
    __half2 p = __floats2half2_rn(a, b);
    return *reinterpret_cast<uint32_t*>(&p);
}

// ---------------------------------------------------------------------------
// Fused prep: x, wq, wk, wv, wo -> fp16 (single). One launch.
// ---------------------------------------------------------------------------
#define X4C (1 << 21)   // MROWS*HIDDEN/4
#define W4C (1 << 20)   // HIDDEN*HIDDEN/4

__global__ __launch_bounds__(256)
void prep_kernel(const float* __restrict__ x,  __half* __restrict__ xh,
                 const float* __restrict__ wq, __half* __restrict__ wqh,
                 const float* __restrict__ wk, __half* __restrict__ wkh,
                 const float* __restrict__ wv, __half* __restrict__ wvh,
                 const float* __restrict__ wo, __half* __restrict__ woh)
{
    const int i = blockIdx.x * blockDim.x + threadIdx.x;
    const float* src;
    __half* dst;
    int e;
    if (i < X4C) {
        src = x; dst = xh; e = i;
    } else {
        const int j = i - X4C;
        const int w = j >> 20;
        e = j & (W4C - 1);
        src = (w == 0) ? wq : (w == 1) ? wk : (w == 2) ? wv : wo;
        dst = (w == 0) ? wqh : (w == 1) ? wkh : (w == 2) ? wvh : woh;
    }
    float4 v = reinterpret_cast<const float4*>(src)[e];
    uint32_t* dp = reinterpret_cast<uint32_t*>(dst) + e * 2;
    dp[0] = pack_h2(v.x, v.y);
    dp[1] = pack_h2(v.z, v.w);
}

// ---------------------------------------------------------------------------
// HMMA fp16 GEMM, single-term weights. KCHUNK=32, ROWB=80, 3-STAGE ring
// (one barrier per chunk — R15-verified). Warp layout 4(m) x 2(n):
// warp tile 32x64 -> per k16 step 6 LDSM feed 16 MMAs (ratio 2.67 vs 2.0).
// MODE 0: fp32 out row-major. MODE 1: fused QKV (N=3*HIDDEN, region scatter).
// CTA 128x128, 256 threads, 2 CTAs/SM (regs<=128, smem 60KB).
// ---------------------------------------------------------------------------
#define GK      HIDDEN
#define KCHUNK  32
#define NCHNK   (GK / KCHUNK)    // 64
#define ROWB    80
#define TILE_B  (128 * ROWB)     // 10240
#define STAGE_B (2 * TILE_B)     // A + B = 20480
#define SMEM_GEMM (3 * STAGE_B)  // 61440

template <int MODE>
__global__ __launch_bounds__(256, 2)
void gemm_f16_kernel(const __half* __restrict__ Ah,
                     const __half* __restrict__ W0,
                     const __half* __restrict__ W1,
                     const __half* __restrict__ W2,
                     const float* __restrict__ b0p,
                     const float* __restrict__ b1p,
                     const float* __restrict__ b2p,
                     float* __restrict__ C,
                     __half* __restrict__ C0,
                     __half* __restrict__ C1,
                     __half* __restrict__ C2,
                     float qscale)
{
    extern __shared__ char smem[];
    const uint32_t sb = smem_u32(smem);
    const int tid = threadIdx.x;
    const int wid = tid >> 5;
    const int lid = tid & 31;

    const int rowBase = blockIdx.y * 128;
    const int colBase = blockIdx.x * 128;

    // Region select (uniform per CTA)
    const __half* Wsel;
    const float*  bsel;
    float outScale = 1.0f;
    int colLocal = colBase;
    if (MODE == 1) {
        const int region = colBase >> 11;
        colLocal = colBase & (HIDDEN - 1);
        Wsel = (region == 0) ? W0 : (region == 1) ? W1 : W2;
        bsel = (region == 0) ? b0p : (region == 1) ? b1p : b2p;
        if (region == 0) outScale = qscale;
    } else {
        Wsel = W0; bsel = b0p;
    }

    // Loader: 2 threads per row, 2x16B each
    const int lr  = tid >> 1;
    const int lc2 = (tid & 1) * 2;
    const __half* pA = Ah   + (size_t)(rowBase  + lr) * GK + lc2 * 8;
    const __half* pB = Wsel + (size_t)(colLocal + lr) * GK + lc2 * 8;
    const uint32_t soff = (uint32_t)lr * ROWB + lc2 * 16;

    auto load_chunk = [&](int c, int st) {
        const uint32_t sg = sb + st * STAGE_B;
        const int e = c * KCHUNK;
        CP_ASYNC16(sg + soff,                 pA + e);
        CP_ASYNC16(sg + soff + 16,            pA + e + 8);
        CP_ASYNC16(sg + TILE_B + soff,        pB + e);
        CP_ASYNC16(sg + TILE_B + soff + 16,   pB + e + 8);
        CP_ASYNC_COMMIT();
    };

    // Warp tiling: 4 (m) x 2 (n), warp tile 32x64
    const int mbase = (wid >> 1) * 32;
    const int nbase = (wid & 1) * 64;

    const int mi   = lid >> 3;
    const int tr   = lid & 7;
    const int a_r8 = (mi & 1) * 8;
    const int a_k8 = (mi >> 1) * 8;
    const int b_n8 = (mi >> 1) * 8;
    const int b_k8 = (mi & 1) * 8;

    float acc[2][8][4];
#pragma unroll
    for (int i = 0; i < 2; i++)
#pragma unroll
        for (int j = 0; j < 8; j++)
#pragma unroll
            for (int r = 0; r < 4; r++) acc[i][j][r] = 0.0f;

    load_chunk(0, 0);
    load_chunk(1, 1);

    int stc = 0;   // compute stage for chunk c
    int stl = 2;   // load stage for chunk c+2
    for (int c = 0; c < NCHNK; c++) {
        if (c == NCHNK - 1) { CP_ASYNC_WAIT0(); } else { CP_ASYNC_WAIT1(); }
        __syncthreads();
        if (c + 2 < NCHNK) load_chunk(c + 2, stl);

        const uint32_t sg = sb + stc * STAGE_B;

#pragma unroll
        for (int ks = 0; ks < 2; ks++) {
            uint32_t B_r[16];
#pragma unroll
            for (int bt = 0; bt < 4; bt++) {
                const uint32_t off =
                    (uint32_t)(nbase + bt * 16 + b_n8 + tr) * ROWB +
                    (uint32_t)(ks * 16 + b_k8) * 2;
                LDSM_X4(&B_r[bt * 4], sg + TILE_B + off);
            }
#pragma unroll
            for (int mt = 0; mt < 2; mt++) {
                uint32_t A_r[4];
                const uint32_t off =
                    (uint32_t)(mbase + mt * 16 + a_r8 + tr) * ROWB +
                    (uint32_t)(ks * 16 + a_k8) * 2;
                LDSM_X4(A_r, sg + off);
#pragma unroll
                for (int nt = 0; nt < 8; nt++)
                    MMA_F16(acc[mt][nt], A_r, &B_r[nt * 2]);
            }
        }
        stc = (stc == 2) ? 0 : stc + 1;
        stl = (stl == 2) ? 0 : stl + 1;
    }

    // ---- epilogue ----
    __half* Cout = nullptr;
    if (MODE == 1) {
        const int region = colBase >> 11;
        Cout = (region == 0) ? C0 : (region == 1) ? C1 : C2;
    }
    const int er = lid >> 2;
    const int ec = (lid & 3) * 2;
#pragma unroll
    for (int mt = 0; mt < 2; mt++) {
#pragma unroll
        for (int nt = 0; nt < 8; nt++) {
            const int col = colLocal + nbase + nt * 8 + ec;
            const float b0 = __ldg(&bsel[col]);
            const float b1 = __ldg(&bsel[col + 1]);
#pragma unroll
            for (int h = 0; h < 2; h++) {
                const int row = rowBase + mbase + mt * 16 + er + h * 8;
                const float vx = (acc[mt][nt][h * 2 + 0] + b0) * outScale;
                const float vy = (acc[mt][nt][h * 2 + 1] + b1) * outScale;
                if (MODE == 0) {
                    float2 v; v.x = vx; v.y = vy;
                    *reinterpret_cast<float2*>(C + (size_t)row * HIDDEN + col) = v;
                } else {
                    const int b  = row >> 11;
                    const int s  = row & (SEQ - 1);
                    const int hh = col >> 7;
                    const int d  = col & (HEAD_DIM - 1);
                    const size_t idx =
                        ((size_t)(b * HEADS + hh) * SEQ + s) * HEAD_DIM + d;
                    *reinterpret_cast<uint32_t*>(Cout + idx) = pack_h2(vx, vy);
                }
            }
        }
    }
}

// ---------------------------------------------------------------------------
// HMMA flash attention, fp16, static-max softmax, 32 q-rows/warp, BQ=128.
// (unchanged — at ~295 TF/s, near the legacy-HMMA pipe ceiling)
// ---------------------------------------------------------------------------
#define FPIT     272
#define F_QB     (128 * FPIT)
#define F_KVT    (64 * FPIT)
#define F_STAGE  (2 * F_KVT)
#define F_ST0    F_QB
#define SMEM_FLASH (F_QB + 2 * F_STAGE)  // 104448
#define NT       (SEQ / 64)

__global__ __launch_bounds__(128, 2)
void flash_hmma_kernel(const __half* __restrict__ qh,
                       const __half* __restrict__ kh,
                       const __half* __restrict__ vh,
                       __half* __restrict__ aoh)
{
    extern __shared__ char smem[];
    const uint32_t sb = smem_u32(smem);
    const int tid = threadIdx.x;
    const int wid = tid >> 5;
    const int lid = tid & 31;

    const int bh = blockIdx.y;
    const int q0 = blockIdx.x * 128;
    const int b  = bh >> 4;
    const int hh = bh & (HEADS - 1);
    const size_t hd = (size_t)bh * SEQ * HEAD_DIM;

    const int mi   = lid >> 3;
    const int tr   = lid & 7;
    const int a_r8 = (mi & 1) * 8;
    const int a_k8 = (mi >> 1) * 8;
    const int b_n8 = (mi >> 1) * 8;
    const int b_k8 = (mi & 1) * 8;
    const int w32  = wid * 32;

    auto load_q = [&]() {
        const size_t srow = hd + (size_t)(q0 + tid) * HEAD_DIM;
        const uint32_t d0 = sb + (uint32_t)tid * FPIT;
#pragma unroll
        for (int j = 0; j < 16; j++)
            CP_ASYNC16(d0 + j * 16, qh + srow + j * 8);
    };
    const int l_lr = tid >> 1, l_lc = tid & 1;
    auto load_kv = [&](int kt) {
        const size_t srow = hd + (size_t)(kt * 64 + l_lr) * HEAD_DIM + l_lc * 64;
        const uint32_t base = sb + F_ST0 + (kt & 1) * F_STAGE +
                              (uint32_t)l_lr * FPIT + l_lc * 128;
#pragma unroll
        for (int j = 0; j < 8; j++) {
            CP_ASYNC16(base + j * 16,         kh + srow + j * 8);
            CP_ASYNC16(base + F_KVT + j * 16, vh + srow + j * 8);
        }
    };

    auto qk_tile = [&](float (&dst)[16][4], int kt) {
        const uint32_t kbase = sb + F_ST0 + (kt & 1) * F_STAGE;
#pragma unroll
        for (int j = 0; j < 16; j++)
#pragma unroll
            for (int r = 0; r < 4; r++) dst[j][r] = 0.0f;
#pragma unroll
        for (int ks = 0; ks < 8; ks++) {
            uint32_t qf[2][4];
#pragma unroll
            for (int qg = 0; qg < 2; qg++)
                LDSM_X4(qf[qg], sb + (uint32_t)(w32 + qg * 16 + a_r8 + tr) * FPIT +
                                 (uint32_t)(ks * 16 + a_k8) * 2);
#pragma unroll
            for (int ng = 0; ng < 4; ng++) {
                uint32_t kf[4];
                LDSM_X4(kf, kbase + (uint32_t)(ng * 16 + b_n8 + tr) * FPIT +
                             (uint32_t)(ks * 16 + b_k8) * 2);
#pragma unroll
                for (int qg = 0; qg < 2; qg++) {
                    MMA_F16(dst[qg * 8 + 2 * ng],     qf[qg], &kf[0]);
                    MMA_F16(dst[qg * 8 + 2 * ng + 1], qf[qg], &kf[2]);
                }
            }
        }
    };

    float oacc[2][16][4];
#pragma unroll
    for (int g = 0; g < 2; g++)
#pragma unroll
        for (int i = 0; i < 16; i++)
#pragma unroll
            for (int r = 0; r < 4; r++) oacc[g][i][r] = 0.0f;

    float m[4];
    float rl[4] = {0.f, 0.f, 0.f, 0.f};

    auto sm_pv = [&](float (&cur)[16][4], int t) {
        const uint32_t vbase = sb + F_ST0 + (t & 1) * F_STAGE + F_KVT;
#pragma unroll
        for (int k2 = 0; k2 < 4; k2++) {
            uint32_t ph[2][4];
#pragma unroll
            for (int qg = 0; qg < 2; qg++) {
#pragma unroll
                for (int half = 0; half < 2; half++) {
                    const int j = 2 * k2 + half;
                    float p0 = ex2(cur[qg * 8 + j][0] - m[qg * 2]);
                    float p1 = ex2(cur[qg * 8 + j][1] - m[qg * 2]);
                    float p2 = ex2(cur[qg * 8 + j][2] - m[qg * 2 + 1]);
                    float p3 = ex2(cur[qg * 8 + j][3] - m[qg * 2 + 1]);
                    rl[qg * 2]     += p0 + p1;
                    rl[qg * 2 + 1] += p2 + p3;
                    ph[qg][half * 2 + 0] = pack_h2(p0, p1);
                    ph[qg][half * 2 + 1] = pack_h2(p2, p3);
                }
            }
#pragma unroll
            for (int nv = 0; nv < 8; nv++) {
                uint32_t vf[4];
                LDSM_X4_T(vf, vbase + (uint32_t)(k2 * 16 + a_r8 + tr) * FPIT +
                               (uint32_t)(nv * 16 + a_k8) * 2);
#pragma unroll
                for (int qg = 0; qg < 2; qg++) {
                    MMA_F16(oacc[qg][2 * nv],     ph[qg], &vf[0]);
                    MMA_F16(oacc[qg][2 * nv + 1], ph[qg], &vf[2]);
                }
            }
        }
    };

    float sacc[16][4];

    load_q(); load_kv(0); CP_ASYNC_COMMIT();
    load_kv(1); CP_ASYNC_COMMIT();
    CP_ASYNC_WAIT1();
    __syncthreads();

    qk_tile(sacc, 0);
#pragma unroll
    for (int qg = 0; qg < 2; qg++) {
        float mx0 = -1e30f, mx1 = -1e30f;
#pragma unroll
        for (int j = 0; j < 8; j++) {
            mx0 = fmaxf(mx0, fmaxf(sacc[qg * 8 + j][0], sacc[qg * 8 + j][1]));
            mx1 = fmaxf(mx1, fmaxf(sacc[qg * 8 + j][2], sacc[qg * 8 + j][3]));
        }
        mx0 = fmaxf(mx0, __shfl_xor_sync(0xffffffffu, mx0, 1));
        mx0 = fmaxf(mx0, __shfl_xor_sync(0xffffffffu, mx0, 2));
        mx1 = fmaxf(mx1, __shfl_xor_sync(0xffffffffu, mx1, 1));
        mx1 = fmaxf(mx1, __shfl_xor_sync(0xffffffffu, mx1, 2));
        m[qg * 2] = mx0; m[qg * 2 + 1] = mx1;
    }
    sm_pv(sacc, 0);
    __syncthreads();
    load_kv(2); CP_ASYNC_COMMIT();

    for (int t = 1; t < NT; t++) {
        if (t == NT - 1) { CP_ASYNC_WAIT0(); } else { CP_ASYNC_WAIT1(); }
        __syncthreads();
        qk_tile(sacc, t);
        sm_pv(sacc, t);
        __syncthreads();
        if (t + 2 < NT) { load_kv(t + 2); CP_ASYNC_COMMIT(); }
    }

#pragma unroll
    for (int i = 0; i < 4; i++) {
        rl[i] += __shfl_xor_sync(0xffffffffu, rl[i], 1);
        rl[i] += __shfl_xor_sync(0xffffffffu, rl[i], 2);
    }
    const int dc = 2 * (lid & 3);
#pragma unroll
    for (int qg = 0; qg < 2; qg++) {
        const float i0 = 1.0f / rl[qg * 2];
        const float i1 = 1.0f / rl[qg * 2 + 1];
        const int r0 = w32 + qg * 16 + (lid >> 2);
        const size_t ob0 = ((size_t)b * SEQ + (q0 + r0)) * HIDDEN + hh * HEAD_DIM;
        const size_t ob1 = ((size_t)b * SEQ + (q0 + r0 + 8)) * HIDDEN + hh * HEAD_DIM;
#pragma unroll
        for (int nt = 0; nt < 16; nt++) {
            const int d = nt * 8 + dc;
            *reinterpret_cast<uint32_t*>(aoh + ob0 + d) =
                pack_h2(oacc[qg][nt][0] * i0, oacc[qg][nt][1] * i0);
            *reinterpret_cast<uint32_t*>(aoh + ob1 + d) =
                pack_h2(oacc[qg][nt][2] * i1, oacc[qg][nt][3] * i1);
        }
    }
}

// ---------------------------------------------------------------------------
extern "C" void kernel_launch(void* const* d_in, const int* in_sizes, int n_in,
                              void* d_out, int out_size)
{
    const float* x  = (const float*)d_in[0];
    const float* wq = (const float*)d_in[1];
    const float* bq = (const float*)d_in[2];
    const float* wk = (const float*)d_in[3];
    const float* bk = (const float*)d_in[4];
    const float* wv = (const float*)d_in[5];
    const float* bv = (const float*)d_in[6];
    const float* wo = (const float*)d_in[7];
    const float* bo = (const float*)d_in[8];
    float* out = (float*)d_out;

    __half *qh, *kh, *vh, *aoh, *xh, *wqh, *wkh, *wvh, *woh;
    cudaGetSymbolAddress((void**)&qh,  g_qh);
    cudaGetSymbolAddress((void**)&kh,  g_kh);
    cudaGetSymbolAddress((void**)&vh,  g_vh);
    cudaGetSymbolAddress((void**)&aoh, g_aoh);
    cudaGetSymbolAddress((void**)&xh,  g_xh);
    cudaGetSymbolAddress((void**)&wqh, g_wqh);
    cudaGetSymbolAddress((void**)&wkh, g_wkh);
    cudaGetSymbolAddress((void**)&wvh, g_wvh);
    cudaGetSymbolAddress((void**)&woh, g_woh);

    const int prep_blocks = (X4C + 4 * W4C + 255) / 256;
    prep_kernel<<<prep_blocks, 256>>>(x, xh, wq, wqh, wk, wkh, wv, wvh, wo, woh);

    cudaFuncSetAttribute((const void*)gemm_f16_kernel<0>,
                         cudaFuncAttributeMaxDynamicSharedMemorySize, SMEM_GEMM);
    cudaFuncSetAttribute((const void*)gemm_f16_kernel<1>,
                         cudaFuncAttributeMaxDynamicSharedMemorySize, SMEM_GEMM);
    cudaFuncSetAttribute((const void*)flash_hmma_kernel,
                         cudaFuncAttributeMaxDynamicSharedMemorySize, SMEM_FLASH);

    const float qscale = 0.12751879721578587f;   // 1/sqrt(128) * log2(e)

    // Fused QKV projection: N = 3*HIDDEN
    const dim3 gqkv(3 * HIDDEN / 128, MROWS / 128);   // (48, 32)
    gemm_f16_kernel<1><<<gqkv, 256, SMEM_GEMM>>>(
        xh, wqh, wkh, wvh, bq, bk, bv,
        nullptr, qh, kh, vh, qscale);

    const dim3 fg(SEQ / 128, BATCH * HEADS);          // (16, 32)
    flash_hmma_kernel<<<fg, 128, SMEM_FLASH>>>(qh, kh, vh, aoh);

    // O projection: fp32 out, single-term
    const dim3 go(HIDDEN / 128, MROWS / 128);         // (16, 32)
    gemm_f16_kernel<0><<<go, 256, SMEM_GEMM>>>(
        aoh, woh, nullptr, nullptr, bo, nullptr, nullptr,
        out, nullptr, nullptr, nullptr, 1.0f);
}